// round 3
// baseline (speedup 1.0000x reference)
#include <cuda_runtime.h>
#include <cuda_bf16.h>

#define Bv 2
#define Cv 36
#define Hv 512
#define Wv 512
#define Kv 9

// Transposed features: [B, H, W, C]; one pixel = 144B contiguous.
__device__ float g_featT[(size_t)Bv * Hv * Wv * Cv];

// ---------------------------------------------------------------------------
// Transpose [B,C,H,W] -> [B,H,W,C].
// ---------------------------------------------------------------------------
__global__ __launch_bounds__(256) void transpose_kernel(const float* __restrict__ feat) {
    __shared__ float tile[Cv][129];
    int b = blockIdx.z;
    int h = blockIdx.y;
    int w0 = blockIdx.x * 128;

    for (int idx = threadIdx.x; idx < Cv * 128; idx += 256) {
        int c = idx >> 7;
        int w = idx & 127;
        tile[c][w] = feat[(((size_t)b * Cv + c) * Hv + h) * Wv + w0 + w];
    }
    __syncthreads();

    float* outp = g_featT + (((size_t)b * Hv + h) * Wv + w0) * Cv;
    for (int e = threadIdx.x; e < 128 * Cv; e += 256) {
        int w = e / Cv;
        int c = e - w * Cv;
        outp[e] = tile[c][w];
    }
}

// ---------------------------------------------------------------------------
// Eval kernel. Block = 128 threads = 4 warps; each warp owns 32 x-consecutive
// pixels. Per candidate:
//   load phase : for each pixel p, 18 lanes fetch the two 144B feature rows
//                (y-rows yb,yb+1; columns xb,xb+1; 36 ch), blend in y in-lane,
//                then blend in x via shfl_down(9) (lane j has lo-quad,
//                lane j+9 the matching hi-quad). Lanes 0-8 store the 36
//                final floats to padded smem.
//   compute    : lane p reads its 9 float4 (conflict-free) and accumulates
//                the 9 group-pair L1 distances vs its register-resident F.
// ---------------------------------------------------------------------------
#define PITCH 44  // 36 data + 8 pad words; 44 mod 32 = 12 -> conflict-free LDS.128

__global__ __launch_bounds__(128, 5) void eval_kernel(
    const float* __restrict__ offx,
    const float* __restrict__ offy,
    float* __restrict__ out)
{
    __shared__ float stage[4][32 * PITCH];

    const int tid  = blockIdx.x * 128 + threadIdx.x;
    const int lane = threadIdx.x & 31;
    const int wid  = threadIdx.x >> 5;
    const int x = tid & (Wv - 1);
    const int y = (tid >> 9) & (Hv - 1);
    const int b = tid >> 18;

    float* buf = stage[wid];
    const char* fb = (const char*)g_featT;
    const unsigned laneoff = (unsigned)lane << 4;

    // ---- Cooperative F load: warp's 32 pixels = 4608B contiguous. ----
    // Read 288 float4s coalesced, scatter into padded smem, read back.
    {
        const float4* src = reinterpret_cast<const float4*>(
            g_featT + (((size_t)b * Hv + y) * Wv + (x & ~31)) * Cv);
#pragma unroll
        for (int q = 0; q < 9; q++) {
            int f = lane + 32 * q;
            int p = f / 9;
            int i = f - 9 * p;
            float4 v = src[f];
            *reinterpret_cast<float4*>(buf + p * PITCH + 4 * i) = v;
        }
    }
    __syncwarp();

    float4 F[9];
#pragma unroll
    for (int i = 0; i < 9; i++)
        F[i] = *reinterpret_cast<const float4*>(buf + lane * PITCH + 4 * i);
    __syncwarp();

    float m = -1e30f, se = 0.f, sx = 0.f, sy = 0.f;

    const size_t obase = (size_t)b * (Kv * Hv * Wv) + (size_t)y * Wv + x;
    const size_t ostride = (size_t)Hv * Wv;

    for (int k = 0; k < Kv; k++) {
        const float oxk = __ldg(offx + obase + (size_t)k * ostride);
        const float oyk = __ldg(offy + obase + (size_t)k * ostride);

        float rx = fminf(fmaxf((float)x + oxk, 0.f), (float)(Wv - 1));
        float ry = fminf(fmaxf((float)y + oyk, 0.f), (float)(Hv - 1));
        int xb = min((int)floorf(rx), Wv - 2);
        int yb = min((int)floorf(ry), Hv - 2);
        float wx = rx - (float)xb;   // in [0,1]
        float wy = ry - (float)yb;
        unsigned off = (unsigned)(((b * Hv + yb) * Wv + xb)) * 144u;

        // ---- load phase ----
#pragma unroll 8
        for (int p = 0; p < 32; p++) {
            unsigned off_p = __shfl_sync(0xffffffffu, off, p);
            float    wy_p  = __shfl_sync(0xffffffffu, wy,  p);
            float    wx_p  = __shfl_sync(0xffffffffu, wx,  p);

            float4 t = make_float4(0.f, 0.f, 0.f, 0.f);
            if (lane < 18) {
                float4 r0 = *reinterpret_cast<const float4*>(fb + off_p + laneoff);
                float4 r1 = *reinterpret_cast<const float4*>(
                    fb + off_p + laneoff + (unsigned)(Wv * Cv * 4));
                t.x = fmaf(wy_p, r1.x - r0.x, r0.x);
                t.y = fmaf(wy_p, r1.y - r0.y, r0.y);
                t.z = fmaf(wy_p, r1.z - r0.z, r0.z);
                t.w = fmaf(wy_p, r1.w - r0.w, r0.w);
            }
            // x-blend: lane j (<9) holds lo-quad, lane j+9 holds hi-quad.
            float hx = __shfl_down_sync(0xffffffffu, t.x, 9);
            float hy = __shfl_down_sync(0xffffffffu, t.y, 9);
            float hz = __shfl_down_sync(0xffffffffu, t.z, 9);
            float hw = __shfl_down_sync(0xffffffffu, t.w, 9);
            if (lane < 9) {
                float4 a;
                a.x = fmaf(wx_p, hx - t.x, t.x);
                a.y = fmaf(wx_p, hy - t.y, t.y);
                a.z = fmaf(wx_p, hz - t.z, t.z);
                a.w = fmaf(wx_p, hw - t.w, t.w);
                *reinterpret_cast<float4*>(buf + p * PITCH + lane * 4) = a;
            }
        }
        __syncwarp();

        // ---- compute phase ----
        float s[9];
#pragma unroll
        for (int i = 0; i < 9; i++) s[i] = 0.f;

        const float* mya = buf + lane * PITCH;
#pragma unroll
        for (int i = 0; i < 9; i++) {
            float4 a = *reinterpret_cast<const float4*>(mya + 4 * i);
            const int gp = i / 3;       // sampled-channel group
            const int r  = i - gp * 3;  // float4 index within group
#pragma unroll
            for (int g = 0; g < 3; g++) {
                float4 f = F[3 * g + r];
                s[3 * g + gp] += fabsf(f.x - a.x) + fabsf(f.y - a.y)
                               + fabsf(f.z - a.z) + fabsf(f.w - a.w);
            }
        }

        float smin = s[0];
#pragma unroll
        for (int i = 1; i < 9; i++) smin = fminf(smin, s[i]);

        float t = smin * (-1000.f / 12.f);

        if (t > m) {
            float c = __expf(m - t);
            se *= c; sx *= c; sy *= c;
            m = t;
        }
        float e = __expf(t - m);
        se += e;
        sx = fmaf(e, oxk, sx);
        sy = fmaf(e, oyk, sy);

        __syncwarp();  // stage reuse barrier before next candidate
    }

    float ox = sx / se;
    float oy = sy / se;
    ox = fminf(fmaxf(ox + (float)x, 0.f), (float)(Wv - 1)) - (float)x;
    oy = fminf(fmaxf(oy + (float)y, 0.f), (float)(Hv - 1)) - (float)y;

    const size_t pix = ((size_t)b * Hv + y) * Wv + x;
    out[pix] = ox;
    out[(size_t)Bv * Hv * Wv + pix] = oy;
}

extern "C" void kernel_launch(void* const* d_in, const int* in_sizes, int n_in,
                              void* d_out, int out_size) {
    const float* features = (const float*)d_in[0];
    const float* offset_x = (const float*)d_in[1];
    const float* offset_y = (const float*)d_in[2];
    float* out = (float*)d_out;

    dim3 tgrid(Wv / 128, Hv, Bv);
    transpose_kernel<<<tgrid, 256>>>(features);

    int total = Bv * Hv * Wv;
    eval_kernel<<<total / 128, 128>>>(offset_x, offset_y, out);
}

// round 4
// speedup vs baseline: 1.5233x; 1.5233x over previous
#include <cuda_runtime.h>
#include <cuda_bf16.h>

#define Bv 2
#define Cv 36
#define Hv 512
#define Wv 512
#define Kv 9

// Transposed features: [B, H, W, C]; one pixel = 144B contiguous.
__device__ float g_featT[(size_t)Bv * Hv * Wv * Cv];

// ---------------------------------------------------------------------------
// Transpose [B,C,H,W] -> [B,H,W,C].
// ---------------------------------------------------------------------------
__global__ __launch_bounds__(256) void transpose_kernel(const float* __restrict__ feat) {
    __shared__ float tile[Cv][129];
    int b = blockIdx.z;
    int h = blockIdx.y;
    int w0 = blockIdx.x * 128;

    for (int idx = threadIdx.x; idx < Cv * 128; idx += 256) {
        int c = idx >> 7;
        int w = idx & 127;
        tile[c][w] = feat[(((size_t)b * Cv + c) * Hv + h) * Wv + w0 + w];
    }
    __syncthreads();

    float* outp = g_featT + (((size_t)b * Hv + h) * Wv + w0) * Cv;
    for (int e = threadIdx.x; e < 128 * Cv; e += 256) {
        int w = e / Cv;
        int c = e - w * Cv;
        outp[e] = tile[c][w];
    }
}

// ---------------------------------------------------------------------------
// Eval kernel (round-2 structure). Block = 128 threads = 4 warps; each warp
// owns 32 x-consecutive pixels.
//  - F is read from the ORIGINAL [B,C,H,W] layout: 36 coalesced scalar loads
//    (1 wavefront each), no staging.
//  - Per candidate: 18 lanes fetch the 288B y-row-pair per pixel, blend in y,
//    store to padded smem; compute phase x-blends from smem and accumulates
//    the 9 group-pair L1 distances.
// ---------------------------------------------------------------------------
#define PITCH 76  // 72 data + 4 pad words; 76 mod 32 = 12 -> conflict-free

__global__ __launch_bounds__(128, 5) void eval_kernel(
    const float* __restrict__ feat,   // original [B,C,H,W]
    const float* __restrict__ offx,
    const float* __restrict__ offy,
    float* __restrict__ out)
{
    __shared__ float stage[4][32 * PITCH];

    const int tid  = blockIdx.x * 128 + threadIdx.x;
    const int lane = threadIdx.x & 31;
    const int wid  = threadIdx.x >> 5;
    const int x = tid & (Wv - 1);
    const int y = (tid >> 9) & (Hv - 1);
    const int b = tid >> 18;

    float* buf = stage[wid];
    const char* fb = (const char*)g_featT;
    const unsigned laneoff = (unsigned)lane << 4;

    // ---- F: 36 coalesced scalar loads from original layout ----
    float F[Cv];
    {
        const float* fp = feat + (size_t)b * (Cv * Hv * Wv) + (size_t)y * Wv + x;
#pragma unroll
        for (int c = 0; c < Cv; c++)
            F[c] = __ldg(fp + (size_t)c * (Hv * Wv));
    }

    float m = -1e30f, se = 0.f, sx = 0.f, sy = 0.f;

    const size_t obase = (size_t)b * (Kv * Hv * Wv) + (size_t)y * Wv + x;
    const size_t ostride = (size_t)Hv * Wv;

    for (int k = 0; k < Kv; k++) {
        const float oxk = __ldg(offx + obase + (size_t)k * ostride);
        const float oyk = __ldg(offy + obase + (size_t)k * ostride);

        float rx = fminf(fmaxf((float)x + oxk, 0.f), (float)(Wv - 1));
        float ry = fminf(fmaxf((float)y + oyk, 0.f), (float)(Hv - 1));
        int xb = min((int)floorf(rx), Wv - 2);
        int yb = min((int)floorf(ry), Hv - 2);
        float wx = rx - (float)xb;   // in [0,1]
        float wy = ry - (float)yb;
        unsigned off = (unsigned)(((b * Hv + yb) * Wv + xb)) * 144u;

        // ---- load phase: per pixel, 18 lanes fetch row-pair & y-blend ----
#pragma unroll 8
        for (int p = 0; p < 32; p++) {
            unsigned off_p = __shfl_sync(0xffffffffu, off, p);
            float    wy_p  = __shfl_sync(0xffffffffu, wy,  p);
            if (lane < 18) {
                float4 r0 = *reinterpret_cast<const float4*>(fb + off_p + laneoff);
                float4 r1 = *reinterpret_cast<const float4*>(
                    fb + off_p + laneoff + (unsigned)(Wv * Cv * 4));
                float4 t;
                t.x = fmaf(wy_p, r1.x - r0.x, r0.x);
                t.y = fmaf(wy_p, r1.y - r0.y, r0.y);
                t.z = fmaf(wy_p, r1.z - r0.z, r0.z);
                t.w = fmaf(wy_p, r1.w - r0.w, r0.w);
                *reinterpret_cast<float4*>(buf + p * PITCH + lane * 4) = t;
            }
        }
        __syncwarp();

        // ---- compute phase: lane p x-blends its own pixel from smem ----
        float s[9];
#pragma unroll
        for (int i = 0; i < 9; i++) s[i] = 0.f;

        const float* mybuf = buf + lane * PITCH;
#pragma unroll
        for (int i = 0; i < 9; i++) {
            float4 lo = *reinterpret_cast<const float4*>(mybuf + 4 * i);       // x = xb
            float4 hi = *reinterpret_cast<const float4*>(mybuf + 36 + 4 * i);  // x = xb+1
            float4 a;
            a.x = fmaf(wx, hi.x - lo.x, lo.x);
            a.y = fmaf(wx, hi.y - lo.y, lo.y);
            a.z = fmaf(wx, hi.z - lo.z, lo.z);
            a.w = fmaf(wx, hi.w - lo.w, lo.w);

            const int gp = i / 3;        // sampled-channel group
            const int r  = i - gp * 3;   // quad index within group
#pragma unroll
            for (int g = 0; g < 3; g++) {
                const float* f = F + 12 * g + 4 * r;
                s[3 * g + gp] += fabsf(f[0] - a.x) + fabsf(f[1] - a.y)
                               + fabsf(f[2] - a.z) + fabsf(f[3] - a.w);
            }
        }

        float smin = s[0];
#pragma unroll
        for (int i = 1; i < 9; i++) smin = fminf(smin, s[i]);

        float t = smin * (-1000.f / 12.f);

        if (t > m) {
            float c = __expf(m - t);
            se *= c; sx *= c; sy *= c;
            m = t;
        }
        float e = __expf(t - m);
        se += e;
        sx = fmaf(e, oxk, sx);
        sy = fmaf(e, oyk, sy);

        __syncwarp();  // stage reuse barrier before next candidate
    }

    float ox = sx / se;
    float oy = sy / se;
    ox = fminf(fmaxf(ox + (float)x, 0.f), (float)(Wv - 1)) - (float)x;
    oy = fminf(fmaxf(oy + (float)y, 0.f), (float)(Hv - 1)) - (float)y;

    const size_t pix = ((size_t)b * Hv + y) * Wv + x;
    out[pix] = ox;
    out[(size_t)Bv * Hv * Wv + pix] = oy;
}

extern "C" void kernel_launch(void* const* d_in, const int* in_sizes, int n_in,
                              void* d_out, int out_size) {
    const float* features = (const float*)d_in[0];
    const float* offset_x = (const float*)d_in[1];
    const float* offset_y = (const float*)d_in[2];
    float* out = (float*)d_out;

    dim3 tgrid(Wv / 128, Hv, Bv);
    transpose_kernel<<<tgrid, 256>>>(features);

    int total = Bv * Hv * Wv;
    eval_kernel<<<total / 128, 128>>>(features, offset_x, offset_y, out);
}

// round 9
// speedup vs baseline: 1.6500x; 1.0832x over previous
#include <cuda_runtime.h>
#include <cuda_bf16.h>

#define Bv 2
#define Cv 36
#define Hv 512
#define Wv 512
#define Kv 9

// Transposed features fp32: [B, H, W, C]; one pixel = 144B contiguous.
__device__ float g_featT[(size_t)Bv * Hv * Wv * Cv];

// ---------------------------------------------------------------------------
// Transpose [B,C,H,W] -> [B,H,W,C], float4 writes.
// ---------------------------------------------------------------------------
__global__ __launch_bounds__(256) void transpose_kernel(const float* __restrict__ feat) {
    __shared__ float tile[Cv][129];
    int b = blockIdx.z;
    int h = blockIdx.y;
    int w0 = blockIdx.x * 128;

    for (int idx = threadIdx.x; idx < Cv * 128; idx += 256) {
        int c = idx >> 7;
        int w = idx & 127;
        tile[c][w] = feat[(((size_t)b * Cv + c) * Hv + h) * Wv + w0 + w];
    }
    __syncthreads();

    // 128 pixels x 9 float4 = 1152 vector writes, contiguous region.
    float4* outp = reinterpret_cast<float4*>(
        g_featT + (((size_t)b * Hv + h) * Wv + w0) * Cv);
    for (int e = threadIdx.x; e < 128 * 9; e += 256) {
        int w = e / 9;
        int q = e - w * 9;
        float4 v;
        v.x = tile[4 * q + 0][w];
        v.y = tile[4 * q + 1][w];
        v.z = tile[4 * q + 2][w];
        v.w = tile[4 * q + 3][w];
        outp[e] = v;
    }
}

// ---------------------------------------------------------------------------
// Eval kernel. Block = 128 threads = 4 warps; each warp owns 32 x-consecutive
// pixels. F read coalesced from the ORIGINAL [B,C,H,W] layout (36 wf total).
// Per candidate:
//   load phase : for each pixel p, 18 lanes fetch the 288B y-row-pair
//                (rows yb,yb+1; pixels xb,xb+1; 36 ch), blend in y in-lane,
//                store float4 to padded smem.
//   compute    : lane p x-blends its 72 staged floats and accumulates the 9
//                group-pair L1 distances vs register-resident F.
// ---------------------------------------------------------------------------
#define PITCH 76  // 72 data + 4 pad words; 76 mod 32 = 12 -> conflict-free

__global__ __launch_bounds__(128, 4) void eval_kernel(
    const float* __restrict__ feat,   // original [B,C,H,W]
    const float* __restrict__ offx,
    const float* __restrict__ offy,
    float* __restrict__ out)
{
    __shared__ float stage[4][32 * PITCH];

    const int tid  = blockIdx.x * 128 + threadIdx.x;
    const int lane = threadIdx.x & 31;
    const int wid  = threadIdx.x >> 5;
    const int x = tid & (Wv - 1);
    const int y = (tid >> 9) & (Hv - 1);
    const int b = tid >> 18;

    float* buf = stage[wid];
    const char* fb = (const char*)g_featT;
    const unsigned laneoff = (unsigned)lane << 4;

    // ---- F: 36 coalesced scalar loads from the original layout ----
    float F[Cv];
    {
        const float* fp = feat + (size_t)b * (Cv * Hv * Wv) + (size_t)y * Wv + x;
#pragma unroll
        for (int c = 0; c < Cv; c++)
            F[c] = __ldg(fp + (size_t)c * (Hv * Wv));
    }

    float m = -1e30f, se = 0.f, sx = 0.f, sy = 0.f;

    const size_t obase = (size_t)b * (Kv * Hv * Wv) + (size_t)y * Wv + x;
    const size_t ostride = (size_t)Hv * Wv;

    for (int k = 0; k < Kv; k++) {
        const float oxk = __ldg(offx + obase + (size_t)k * ostride);
        const float oyk = __ldg(offy + obase + (size_t)k * ostride);

        float rx = fminf(fmaxf((float)x + oxk, 0.f), (float)(Wv - 1));
        float ry = fminf(fmaxf((float)y + oyk, 0.f), (float)(Hv - 1));
        int xb = min((int)floorf(rx), Wv - 2);
        int yb = min((int)floorf(ry), Hv - 2);
        float wx = rx - (float)xb;   // [0,1]
        float wy = ry - (float)yb;
        unsigned off = (unsigned)((b * Hv + yb) * Wv + xb) * 144u;

        // ---- load phase: per pixel, 18 lanes fetch row-pair & y-blend ----
#pragma unroll 8
        for (int p = 0; p < 32; p++) {
            unsigned off_p = __shfl_sync(0xffffffffu, off, p);
            float    wy_p  = __shfl_sync(0xffffffffu, wy,  p);
            if (lane < 18) {
                float4 r0 = *reinterpret_cast<const float4*>(fb + off_p + laneoff);
                float4 r1 = *reinterpret_cast<const float4*>(
                    fb + off_p + laneoff + (unsigned)(Wv * Cv * 4));
                float4 t;
                t.x = fmaf(wy_p, r1.x - r0.x, r0.x);
                t.y = fmaf(wy_p, r1.y - r0.y, r0.y);
                t.z = fmaf(wy_p, r1.z - r0.z, r0.z);
                t.w = fmaf(wy_p, r1.w - r0.w, r0.w);
                *reinterpret_cast<float4*>(buf + p * PITCH + lane * 4) = t;
            }
        }
        __syncwarp();

        // ---- compute phase: lane p x-blends its own pixel from smem ----
        float s[9];
#pragma unroll
        for (int i = 0; i < 9; i++) s[i] = 0.f;

        const float* mybuf = buf + lane * PITCH;
#pragma unroll
        for (int i = 0; i < 9; i++) {
            float4 lo = *reinterpret_cast<const float4*>(mybuf + 4 * i);       // x = xb
            float4 hi = *reinterpret_cast<const float4*>(mybuf + 36 + 4 * i);  // x = xb+1
            float4 a;
            a.x = fmaf(wx, hi.x - lo.x, lo.x);
            a.y = fmaf(wx, hi.y - lo.y, lo.y);
            a.z = fmaf(wx, hi.z - lo.z, lo.z);
            a.w = fmaf(wx, hi.w - lo.w, lo.w);

            const int gp = i / 3;        // sampled-channel group
            const int r  = i - gp * 3;   // quad index within group
#pragma unroll
            for (int g = 0; g < 3; g++) {
                const float* f = F + 12 * g + 4 * r;
                s[3 * g + gp] += fabsf(f[0] - a.x) + fabsf(f[1] - a.y)
                               + fabsf(f[2] - a.z) + fabsf(f[3] - a.w);
            }
        }

        float smin = s[0];
#pragma unroll
        for (int i = 1; i < 9; i++) smin = fminf(smin, s[i]);

        float t = smin * (-1000.f / 12.f);

        if (t > m) {
            float c = __expf(m - t);
            se *= c; sx *= c; sy *= c;
            m = t;
        }
        float e = __expf(t - m);
        se += e;
        sx = fmaf(e, oxk, sx);
        sy = fmaf(e, oyk, sy);

        __syncwarp();  // stage reuse barrier before next candidate
    }

    float ox = sx / se;
    float oy = sy / se;
    ox = fminf(fmaxf(ox + (float)x, 0.f), (float)(Wv - 1)) - (float)x;
    oy = fminf(fmaxf(oy + (float)y, 0.f), (float)(Hv - 1)) - (float)y;

    const size_t pix = ((size_t)b * Hv + y) * Wv + x;
    out[pix] = ox;
    out[(size_t)Bv * Hv * Wv + pix] = oy;
}

extern "C" void kernel_launch(void* const* d_in, const int* in_sizes, int n_in,
                              void* d_out, int out_size) {
    const float* features = (const float*)d_in[0];
    const float* offset_x = (const float*)d_in[1];
    const float* offset_y = (const float*)d_in[2];
    float* out = (float*)d_out;

    dim3 tgrid(Wv / 128, Hv, Bv);
    transpose_kernel<<<tgrid, 256>>>(features);

    int total = Bv * Hv * Wv;
    eval_kernel<<<total / 128, 128>>>(features, offset_x, offset_y, out);
}

// round 10
// speedup vs baseline: 1.8962x; 1.1492x over previous
#include <cuda_runtime.h>
#include <cuda_bf16.h>

#define Bv 2
#define Cv 36
#define Hv 512
#define Wv 512
#define Kv 9

// Transposed features fp32: [B, H, W, C]; one pixel = 144B contiguous.
__device__ float g_featT[(size_t)Bv * Hv * Wv * Cv];

// ---------------------------------------------------------------------------
// Transpose [B,C,H,W] -> [B,H,W,C], float4 writes.
// ---------------------------------------------------------------------------
__global__ __launch_bounds__(256) void transpose_kernel(const float* __restrict__ feat) {
    __shared__ float tile[Cv][129];
    int b = blockIdx.z;
    int h = blockIdx.y;
    int w0 = blockIdx.x * 128;

    for (int idx = threadIdx.x; idx < Cv * 128; idx += 256) {
        int c = idx >> 7;
        int w = idx & 127;
        tile[c][w] = feat[(((size_t)b * Cv + c) * Hv + h) * Wv + w0 + w];
    }
    __syncthreads();

    float4* outp = reinterpret_cast<float4*>(
        g_featT + (((size_t)b * Hv + h) * Wv + w0) * Cv);
    for (int e = threadIdx.x; e < 128 * 9; e += 256) {
        int w = e / 9;
        int q = e - w * 9;
        float4 v;
        v.x = tile[4 * q + 0][w];
        v.y = tile[4 * q + 1][w];
        v.z = tile[4 * q + 2][w];
        v.w = tile[4 * q + 3][w];
        outp[e] = v;
    }
}

// ---------------------------------------------------------------------------
// Eval kernel. Block = 128 threads = 4 warps; each warp owns 32 x-consecutive
// pixels. F read coalesced from the ORIGINAL [B,C,H,W] layout.
// Per candidate (offsets prefetched one candidate ahead):
//   load phase : flat 576 quad-slots (32 px x 18 quads) over 18 full-width
//                iterations; lane grabs its pixel's (off, wy) via indexed
//                shuffle, fetches the two 16B row pieces, y-blends, stores
//                float4 to padded smem (full 512B STS).
//   compute    : lane p x-blends its 72 staged floats and accumulates the 9
//                group-pair L1 distances vs register-resident F.
// ---------------------------------------------------------------------------
#define PITCH 76  // 72 data + 4 pad words; 76 mod 32 = 12 -> conflict-free

__global__ __launch_bounds__(128, 4) void eval_kernel(
    const float* __restrict__ feat,   // original [B,C,H,W]
    const float* __restrict__ offx,
    const float* __restrict__ offy,
    float* __restrict__ out)
{
    __shared__ float stage[4][32 * PITCH];

    const int tid  = blockIdx.x * 128 + threadIdx.x;
    const int lane = threadIdx.x & 31;
    const int wid  = threadIdx.x >> 5;
    const int x = tid & (Wv - 1);
    const int y = (tid >> 9) & (Hv - 1);
    const int b = tid >> 18;

    float* buf = stage[wid];
    const char* fb = (const char*)g_featT;
    const unsigned rowstride = (unsigned)(Wv * Cv * 4);

    // ---- F: 36 coalesced scalar loads from the original layout ----
    float F[Cv];
    {
        const float* fp = feat + (size_t)b * (Cv * Hv * Wv) + (size_t)y * Wv + x;
#pragma unroll
        for (int c = 0; c < Cv; c++)
            F[c] = __ldg(fp + (size_t)c * (Hv * Wv));
    }

    float m = -1e30f, se = 0.f, sx = 0.f, sy = 0.f;

    const size_t obase = (size_t)b * (Kv * Hv * Wv) + (size_t)y * Wv + x;
    const size_t ostride = (size_t)Hv * Wv;

    // Prefetch candidate 0 offsets.
    float oxk = __ldg(offx + obase);
    float oyk = __ldg(offy + obase);

    for (int k = 0; k < Kv; k++) {
        // Prefetch next candidate's offsets early (overlaps the whole body).
        float ox_n = 0.f, oy_n = 0.f;
        if (k + 1 < Kv) {
            ox_n = __ldg(offx + obase + (size_t)(k + 1) * ostride);
            oy_n = __ldg(offy + obase + (size_t)(k + 1) * ostride);
        }

        float rx = fminf(fmaxf((float)x + oxk, 0.f), (float)(Wv - 1));
        float ry = fminf(fmaxf((float)y + oyk, 0.f), (float)(Hv - 1));
        int xb = min((int)floorf(rx), Wv - 2);
        int yb = min((int)floorf(ry), Hv - 2);
        float wx = rx - (float)xb;   // [0,1]
        float wy = ry - (float)yb;
        unsigned off = (unsigned)((b * Hv + yb) * Wv + xb) * 144u;

        // ---- load phase: 18 full-width iterations over 576 quad-slots ----
#pragma unroll 6
        for (int i = 0; i < 18; i++) {
            int f = 32 * i + lane;
            int p = f / 18;            // pixel within warp
            int j = f - 18 * p;        // quad slot (0..17) within 288B row
            unsigned off_p = __shfl_sync(0xffffffffu, off, p);
            float    wy_p  = __shfl_sync(0xffffffffu, wy,  p);
            const char* base = fb + off_p + ((unsigned)j << 4);
            float4 r0 = *reinterpret_cast<const float4*>(base);
            float4 r1 = *reinterpret_cast<const float4*>(base + rowstride);
            float4 t;
            t.x = fmaf(wy_p, r1.x - r0.x, r0.x);
            t.y = fmaf(wy_p, r1.y - r0.y, r0.y);
            t.z = fmaf(wy_p, r1.z - r0.z, r0.z);
            t.w = fmaf(wy_p, r1.w - r0.w, r0.w);
            *reinterpret_cast<float4*>(buf + p * PITCH + 4 * j) = t;
        }
        __syncwarp();

        // ---- compute phase: lane p x-blends its own pixel from smem ----
        float s[9];
#pragma unroll
        for (int i = 0; i < 9; i++) s[i] = 0.f;

        const float* mybuf = buf + lane * PITCH;
#pragma unroll
        for (int i = 0; i < 9; i++) {
            float4 lo = *reinterpret_cast<const float4*>(mybuf + 4 * i);       // x = xb
            float4 hi = *reinterpret_cast<const float4*>(mybuf + 36 + 4 * i);  // x = xb+1
            float4 a;
            a.x = fmaf(wx, hi.x - lo.x, lo.x);
            a.y = fmaf(wx, hi.y - lo.y, lo.y);
            a.z = fmaf(wx, hi.z - lo.z, lo.z);
            a.w = fmaf(wx, hi.w - lo.w, lo.w);

            const int gp = i / 3;        // sampled-channel group
            const int r  = i - gp * 3;   // quad index within group
#pragma unroll
            for (int g = 0; g < 3; g++) {
                const float* f = F + 12 * g + 4 * r;
                s[3 * g + gp] += fabsf(f[0] - a.x) + fabsf(f[1] - a.y)
                               + fabsf(f[2] - a.z) + fabsf(f[3] - a.w);
            }
        }

        float smin = s[0];
#pragma unroll
        for (int i = 1; i < 9; i++) smin = fminf(smin, s[i]);

        float t = smin * (-1000.f / 12.f);

        if (t > m) {
            float c = __expf(m - t);
            se *= c; sx *= c; sy *= c;
            m = t;
        }
        float e = __expf(t - m);
        se += e;
        sx = fmaf(e, oxk, sx);
        sy = fmaf(e, oyk, sy);

        oxk = ox_n;
        oyk = oy_n;

        __syncwarp();  // stage reuse barrier before next candidate
    }

    float ox = sx / se;
    float oy = sy / se;
    ox = fminf(fmaxf(ox + (float)x, 0.f), (float)(Wv - 1)) - (float)x;
    oy = fminf(fmaxf(oy + (float)y, 0.f), (float)(Hv - 1)) - (float)y;

    const size_t pix = ((size_t)b * Hv + y) * Wv + x;
    out[pix] = ox;
    out[(size_t)Bv * Hv * Wv + pix] = oy;
}

extern "C" void kernel_launch(void* const* d_in, const int* in_sizes, int n_in,
                              void* d_out, int out_size) {
    const float* features = (const float*)d_in[0];
    const float* offset_x = (const float*)d_in[1];
    const float* offset_y = (const float*)d_in[2];
    float* out = (float*)d_out;

    dim3 tgrid(Wv / 128, Hv, Bv);
    transpose_kernel<<<tgrid, 256>>>(features);

    int total = Bv * Hv * Wv;
    eval_kernel<<<total / 128, 128>>>(features, offset_x, offset_y, out);
}

// round 11
// speedup vs baseline: 2.0135x; 1.0618x over previous
#include <cuda_runtime.h>
#include <cuda_bf16.h>

#define Bv 2
#define Cv 36
#define Hv 512
#define Wv 512
#define Kv 9

// Transposed features fp32: [B, H, W, C]; one pixel = 144B contiguous.
__device__ float g_featT[(size_t)Bv * Hv * Wv * Cv];

// ---------------------------------------------------------------------------
// Transpose [B,C,H,W] -> [B,H,W,C], float4 writes.
// ---------------------------------------------------------------------------
__global__ __launch_bounds__(256) void transpose_kernel(const float* __restrict__ feat) {
    __shared__ float tile[Cv][129];
    int b = blockIdx.z;
    int h = blockIdx.y;
    int w0 = blockIdx.x * 128;

    for (int idx = threadIdx.x; idx < Cv * 128; idx += 256) {
        int c = idx >> 7;
        int w = idx & 127;
        tile[c][w] = feat[(((size_t)b * Cv + c) * Hv + h) * Wv + w0 + w];
    }
    __syncthreads();

    float4* outp = reinterpret_cast<float4*>(
        g_featT + (((size_t)b * Hv + h) * Wv + w0) * Cv);
    for (int e = threadIdx.x; e < 128 * 9; e += 256) {
        int w = e / 9;
        int q = e - w * 9;
        float4 v;
        v.x = tile[4 * q + 0][w];
        v.y = tile[4 * q + 1][w];
        v.z = tile[4 * q + 2][w];
        v.w = tile[4 * q + 3][w];
        outp[e] = v;
    }
}

// ---------------------------------------------------------------------------
// Eval kernel. Block = 128 threads = 4 warps; each warp owns 32 x-consecutive
// pixels. F read coalesced from the ORIGINAL [B,C,H,W] layout.
// Per candidate (offsets prefetched one candidate ahead):
//   load phase : flat 288 quad-slots (32 px x 9 channel-quads) over 9
//                full-width iterations. Each lane fetches the 4 bilinear
//                corner quads (xb/xb+1 x yb/yb+1) for its (pixel, quad) slot,
//                completes the FULL bilinear blend in registers, and stores
//                only the 36 final floats. Store word index = 4*f exactly ->
//                perfectly linear 512B STS.128, no padding, conflict-free.
//   compute    : lane p reads its 9 sample quads (stride 144B, conflict-free)
//                and accumulates the 9 group-pair L1 sums vs register F.
// ---------------------------------------------------------------------------
__global__ __launch_bounds__(128, 4) void eval_kernel(
    const float* __restrict__ feat,   // original [B,C,H,W]
    const float* __restrict__ offx,
    const float* __restrict__ offy,
    float* __restrict__ out)
{
    __shared__ float stage[4][32 * 36];

    const int tid  = blockIdx.x * 128 + threadIdx.x;
    const int lane = threadIdx.x & 31;
    const int wid  = threadIdx.x >> 5;
    const int x = tid & (Wv - 1);
    const int y = (tid >> 9) & (Hv - 1);
    const int b = tid >> 18;

    float* buf = stage[wid];
    const char* fb = (const char*)g_featT;
    const unsigned rowstride = (unsigned)(Wv * Cv * 4);   // next y-row

    // ---- F: 36 coalesced scalar loads from the original layout ----
    float F[Cv];
    {
        const float* fp = feat + (size_t)b * (Cv * Hv * Wv) + (size_t)y * Wv + x;
#pragma unroll
        for (int c = 0; c < Cv; c++)
            F[c] = __ldg(fp + (size_t)c * (Hv * Wv));
    }

    float m = -1e30f, se = 0.f, sx = 0.f, sy = 0.f;

    const size_t obase = (size_t)b * (Kv * Hv * Wv) + (size_t)y * Wv + x;
    const size_t ostride = (size_t)Hv * Wv;

    // Prefetch candidate 0 offsets.
    float oxk = __ldg(offx + obase);
    float oyk = __ldg(offy + obase);

    for (int k = 0; k < Kv; k++) {
        float ox_n = 0.f, oy_n = 0.f;
        if (k + 1 < Kv) {
            ox_n = __ldg(offx + obase + (size_t)(k + 1) * ostride);
            oy_n = __ldg(offy + obase + (size_t)(k + 1) * ostride);
        }

        float rx = fminf(fmaxf((float)x + oxk, 0.f), (float)(Wv - 1));
        float ry = fminf(fmaxf((float)y + oyk, 0.f), (float)(Hv - 1));
        int xb = min((int)floorf(rx), Wv - 2);
        int yb = min((int)floorf(ry), Hv - 2);
        float wx = rx - (float)xb;   // [0,1]
        float wy = ry - (float)yb;
        unsigned off = (unsigned)((b * Hv + yb) * Wv + xb) * 144u;

        // ---- load phase: 9 full-width iterations over 288 quad-slots ----
#pragma unroll 3
        for (int i = 0; i < 9; i++) {
            int f = 32 * i + lane;
            int p = f / 9;             // pixel within warp
            int j = f - 9 * p;         // channel-quad (0..8)
            unsigned off_p = __shfl_sync(0xffffffffu, off, p);
            float    wy_p  = __shfl_sync(0xffffffffu, wy,  p);
            float    wx_p  = __shfl_sync(0xffffffffu, wx,  p);
            const char* base = fb + off_p + ((unsigned)j << 4);
            float4 r0l = *reinterpret_cast<const float4*>(base);            // yb , xb
            float4 r0h = *reinterpret_cast<const float4*>(base + 144);      // yb , xb+1
            float4 r1l = *reinterpret_cast<const float4*>(base + rowstride);        // yb+1, xb
            float4 r1h = *reinterpret_cast<const float4*>(base + rowstride + 144);  // yb+1, xb+1
            float4 a;
            {
                float tl = fmaf(wy_p, r1l.x - r0l.x, r0l.x);
                float th = fmaf(wy_p, r1h.x - r0h.x, r0h.x);
                a.x = fmaf(wx_p, th - tl, tl);
            }
            {
                float tl = fmaf(wy_p, r1l.y - r0l.y, r0l.y);
                float th = fmaf(wy_p, r1h.y - r0h.y, r0h.y);
                a.y = fmaf(wx_p, th - tl, tl);
            }
            {
                float tl = fmaf(wy_p, r1l.z - r0l.z, r0l.z);
                float th = fmaf(wy_p, r1h.z - r0h.z, r0h.z);
                a.z = fmaf(wx_p, th - tl, tl);
            }
            {
                float tl = fmaf(wy_p, r1l.w - r0l.w, r0l.w);
                float th = fmaf(wy_p, r1h.w - r0h.w, r0h.w);
                a.w = fmaf(wx_p, th - tl, tl);
            }
            // word index = 36*p + 4*j = 4*f -> linear, conflict-free STS.128
            *reinterpret_cast<float4*>(buf + 4 * f) = a;
        }
        __syncwarp();

        // ---- compute phase: lane p accumulates 9 group-pair L1 sums ----
        float s[9];
#pragma unroll
        for (int i = 0; i < 9; i++) s[i] = 0.f;

        const float* mybuf = buf + 36 * lane;
#pragma unroll
        for (int i = 0; i < 9; i++) {
            float4 a = *reinterpret_cast<const float4*>(mybuf + 4 * i);
            const int gp = i / 3;        // sampled-channel group
            const int r  = i - gp * 3;   // quad index within group
#pragma unroll
            for (int g = 0; g < 3; g++) {
                const float* f = F + 12 * g + 4 * r;
                s[3 * g + gp] += fabsf(f[0] - a.x) + fabsf(f[1] - a.y)
                               + fabsf(f[2] - a.z) + fabsf(f[3] - a.w);
            }
        }

        float smin = s[0];
#pragma unroll
        for (int i = 1; i < 9; i++) smin = fminf(smin, s[i]);

        float t = smin * (-1000.f / 12.f);

        if (t > m) {
            float c = __expf(m - t);
            se *= c; sx *= c; sy *= c;
            m = t;
        }
        float e = __expf(t - m);
        se += e;
        sx = fmaf(e, oxk, sx);
        sy = fmaf(e, oyk, sy);

        oxk = ox_n;
        oyk = oy_n;

        __syncwarp();  // stage reuse barrier before next candidate
    }

    float ox = sx / se;
    float oy = sy / se;
    ox = fminf(fmaxf(ox + (float)x, 0.f), (float)(Wv - 1)) - (float)x;
    oy = fminf(fmaxf(oy + (float)y, 0.f), (float)(Hv - 1)) - (float)y;

    const size_t pix = ((size_t)b * Hv + y) * Wv + x;
    out[pix] = ox;
    out[(size_t)Bv * Hv * Wv + pix] = oy;
}

extern "C" void kernel_launch(void* const* d_in, const int* in_sizes, int n_in,
                              void* d_out, int out_size) {
    const float* features = (const float*)d_in[0];
    const float* offset_x = (const float*)d_in[1];
    const float* offset_y = (const float*)d_in[2];
    float* out = (float*)d_out;

    dim3 tgrid(Wv / 128, Hv, Bv);
    transpose_kernel<<<tgrid, 256>>>(features);

    int total = Bv * Hv * Wv;
    eval_kernel<<<total / 128, 128>>>(features, offset_x, offset_y, out);
}

// round 12
// speedup vs baseline: 2.0894x; 1.0377x over previous
#include <cuda_runtime.h>
#include <cuda_bf16.h>

#define Bv 2
#define Cv 36
#define Hv 512
#define Wv 512
#define Kv 9

// Transposed features fp32: [B, H, W, C]; one pixel = 144B contiguous.
__device__ float g_featT[(size_t)Bv * Hv * Wv * Cv];

// ---------------------------------------------------------------------------
// Transpose [B,C,H,W] -> [B,H,W,C]; float4 reads AND float4 writes.
// ---------------------------------------------------------------------------
__global__ __launch_bounds__(256) void transpose_kernel(const float* __restrict__ feat) {
    __shared__ float tile[Cv][129];
    int b = blockIdx.z;
    int h = blockIdx.y;
    int w0 = blockIdx.x * 128;

    // 36 channels x 32 float4 = 1152 vector reads; warp = one channel row.
    const float4* src = reinterpret_cast<const float4*>(feat);
    for (int i = threadIdx.x; i < Cv * 32; i += 256) {
        int c  = i >> 5;
        int w4 = i & 31;
        float4 v = src[((((size_t)b * Cv + c) * Hv + h) * Wv + w0) / 4 + w4];
        tile[c][4 * w4 + 0] = v.x;
        tile[c][4 * w4 + 1] = v.y;
        tile[c][4 * w4 + 2] = v.z;
        tile[c][4 * w4 + 3] = v.w;
    }
    __syncthreads();

    float4* outp = reinterpret_cast<float4*>(
        g_featT + (((size_t)b * Hv + h) * Wv + w0) * Cv);
    for (int e = threadIdx.x; e < 128 * 9; e += 256) {
        int w = e / 9;
        int q = e - w * 9;
        float4 v;
        v.x = tile[4 * q + 0][w];
        v.y = tile[4 * q + 1][w];
        v.z = tile[4 * q + 2][w];
        v.w = tile[4 * q + 3][w];
        outp[e] = v;
    }
}

// ---------------------------------------------------------------------------
// Eval kernel, software-pipelined over candidates with a double-buffered
// per-warp stage. Block = 128 threads = 4 warps; warp owns 32 x-consecutive
// pixels. F read coalesced from the ORIGINAL [B,C,H,W] layout.
// Iteration k issues load-phase k+1 (buf (k+1)&1) before compute-phase k
// (buf k&1) so LDG latency of k+1 overlaps compute of k.
// ---------------------------------------------------------------------------
__global__ __launch_bounds__(128, 4) void eval_kernel(
    const float* __restrict__ feat,   // original [B,C,H,W]
    const float* __restrict__ offx,
    const float* __restrict__ offy,
    float* __restrict__ out)
{
    __shared__ float stage[4][2][32 * 36];

    const int tid  = blockIdx.x * 128 + threadIdx.x;
    const int lane = threadIdx.x & 31;
    const int wid  = threadIdx.x >> 5;
    const int x = tid & (Wv - 1);
    const int y = (tid >> 9) & (Hv - 1);
    const int b = tid >> 18;

    const char* fb = (const char*)g_featT;
    const unsigned rowstride = (unsigned)(Wv * Cv * 4);   // next y-row

    // ---- F: 36 coalesced scalar loads from the original layout ----
    float F[Cv];
    {
        const float* fp = feat + (size_t)b * (Cv * Hv * Wv) + (size_t)y * Wv + x;
#pragma unroll
        for (int c = 0; c < Cv; c++)
            F[c] = __ldg(fp + (size_t)c * (Hv * Wv));
    }

    // Coordinate computation for one candidate.
    auto coords = [&](float oxk, float oyk, unsigned& off, float& wx, float& wy) {
        float rx = fminf(fmaxf((float)x + oxk, 0.f), (float)(Wv - 1));
        float ry = fminf(fmaxf((float)y + oyk, 0.f), (float)(Hv - 1));
        int xb = min((int)floorf(rx), Wv - 2);
        int yb = min((int)floorf(ry), Hv - 2);
        wx = rx - (float)xb;
        wy = ry - (float)yb;
        off = (unsigned)((b * Hv + yb) * Wv + xb) * 144u;
    };

    // Load phase: 9 full-width iterations over 288 (pixel, channel-quad) slots.
    auto load_phase = [&](unsigned off, float wx, float wy, float* dst) {
#pragma unroll 3
        for (int i = 0; i < 9; i++) {
            int f = 32 * i + lane;
            int p = f / 9;             // pixel within warp
            int j = f - 9 * p;         // channel-quad (0..8)
            unsigned off_p = __shfl_sync(0xffffffffu, off, p);
            float    wy_p  = __shfl_sync(0xffffffffu, wy,  p);
            float    wx_p  = __shfl_sync(0xffffffffu, wx,  p);
            const char* base = fb + off_p + ((unsigned)j << 4);
            float4 r0l = *reinterpret_cast<const float4*>(base);                    // yb  , xb
            float4 r0h = *reinterpret_cast<const float4*>(base + 144);              // yb  , xb+1
            float4 r1l = *reinterpret_cast<const float4*>(base + rowstride);        // yb+1, xb
            float4 r1h = *reinterpret_cast<const float4*>(base + rowstride + 144);  // yb+1, xb+1
            float4 a;
            {
                float tl = fmaf(wy_p, r1l.x - r0l.x, r0l.x);
                float th = fmaf(wy_p, r1h.x - r0h.x, r0h.x);
                a.x = fmaf(wx_p, th - tl, tl);
            }
            {
                float tl = fmaf(wy_p, r1l.y - r0l.y, r0l.y);
                float th = fmaf(wy_p, r1h.y - r0h.y, r0h.y);
                a.y = fmaf(wx_p, th - tl, tl);
            }
            {
                float tl = fmaf(wy_p, r1l.z - r0l.z, r0l.z);
                float th = fmaf(wy_p, r1h.z - r0h.z, r0h.z);
                a.z = fmaf(wx_p, th - tl, tl);
            }
            {
                float tl = fmaf(wy_p, r1l.w - r0l.w, r0l.w);
                float th = fmaf(wy_p, r1h.w - r0h.w, r0h.w);
                a.w = fmaf(wx_p, th - tl, tl);
            }
            *reinterpret_cast<float4*>(dst + 4 * f) = a;   // linear STS.128
        }
    };

    float m = -1e30f, se = 0.f, sx = 0.f, sy = 0.f;

    const size_t obase = (size_t)b * (Kv * Hv * Wv) + (size_t)y * Wv + x;
    const size_t ostride = (size_t)Hv * Wv;

    // ---- prologue: candidate 0 loaded into buf 0 ----
    float ox_c = __ldg(offx + obase);
    float oy_c = __ldg(offy + obase);
    {
        unsigned off0; float wx0, wy0;
        coords(ox_c, oy_c, off0, wx0, wy0);
        load_phase(off0, wx0, wy0, stage[wid][0]);
    }
    float ox_n = __ldg(offx + obase + ostride);
    float oy_n = __ldg(offy + obase + ostride);
    __syncwarp();

    for (int k = 0; k < Kv; k++) {
        // Prefetch k+2 offsets (overlaps everything below).
        float ox_n2 = 0.f, oy_n2 = 0.f;
        if (k + 2 < Kv) {
            ox_n2 = __ldg(offx + obase + (size_t)(k + 2) * ostride);
            oy_n2 = __ldg(offy + obase + (size_t)(k + 2) * ostride);
        }

        // Issue load phase k+1 into the other buffer (overlaps compute k).
        if (k + 1 < Kv) {
            unsigned off; float wx, wy;
            coords(ox_n, oy_n, off, wx, wy);
            load_phase(off, wx, wy, stage[wid][(k + 1) & 1]);
        }

        // ---- compute phase k from buf k&1 ----
        float s[9];
#pragma unroll
        for (int i = 0; i < 9; i++) s[i] = 0.f;

        const float* mybuf = stage[wid][k & 1] + 36 * lane;
#pragma unroll
        for (int i = 0; i < 9; i++) {
            float4 a = *reinterpret_cast<const float4*>(mybuf + 4 * i);
            const int gp = i / 3;        // sampled-channel group
            const int r  = i - gp * 3;   // quad index within group
#pragma unroll
            for (int g = 0; g < 3; g++) {
                const float* f = F + 12 * g + 4 * r;
                s[3 * g + gp] += fabsf(f[0] - a.x) + fabsf(f[1] - a.y)
                               + fabsf(f[2] - a.z) + fabsf(f[3] - a.w);
            }
        }

        float smin = s[0];
#pragma unroll
        for (int i = 1; i < 9; i++) smin = fminf(smin, s[i]);

        float t = smin * (-1000.f / 12.f);

        if (t > m) {
            float c = __expf(m - t);
            se *= c; sx *= c; sy *= c;
            m = t;
        }
        float e = __expf(t - m);
        se += e;
        sx = fmaf(e, ox_c, sx);
        sy = fmaf(e, oy_c, sy);

        ox_c = ox_n;  oy_c = oy_n;
        ox_n = ox_n2; oy_n = oy_n2;

        __syncwarp();  // STS of k+1 visible before its LDS next iteration
    }

    float ox = sx / se;
    float oy = sy / se;
    ox = fminf(fmaxf(ox + (float)x, 0.f), (float)(Wv - 1)) - (float)x;
    oy = fminf(fmaxf(oy + (float)y, 0.f), (float)(Hv - 1)) - (float)y;

    const size_t pix = ((size_t)b * Hv + y) * Wv + x;
    out[pix] = ox;
    out[(size_t)Bv * Hv * Wv + pix] = oy;
}

extern "C" void kernel_launch(void* const* d_in, const int* in_sizes, int n_in,
                              void* d_out, int out_size) {
    const float* features = (const float*)d_in[0];
    const float* offset_x = (const float*)d_in[1];
    const float* offset_y = (const float*)d_in[2];
    float* out = (float*)d_out;

    dim3 tgrid(Wv / 128, Hv, Bv);
    transpose_kernel<<<tgrid, 256>>>(features);

    int total = Bv * Hv * Wv;
    eval_kernel<<<total / 128, 128>>>(features, offset_x, offset_y, out);
}